// round 17
// baseline (speedup 1.0000x reference)
#include <cuda_runtime.h>
#include <cuda_fp16.h>
#include <cstdint>

// ============================================================
// LoRALinear on base sm_103 (no 'a' features):
//   out = (x @ signs^T) * scale + 2 * ((x@A^T) @ B^T)
// Path: SINGLE-PASS fp16 HMMA m16n8k16, f32 accumulate.
// R16: same as R15 (CTA 256x128, 4-stage, single sync/chunk) with the
// issue_lora fill bug fixed (rows are 6x16B = 96 bytes, not 3x16B --
// R15 left stale chunk-60 data in lora columns 24..47 -> 7.7e-2 err).
// ============================================================

#define DINLINE __device__ __forceinline__

// ---------------- scratch (device globals) ----------------
__device__ __half g_xh[8192u * 4096u];   // 64 MB  x in fp16
__device__ __half g_sh[4096u * 4096u];   // 32 MB  signs in fp16 (exact)
__device__ float  g_t [8192 * 16];       // t = x @ A^T (fp32)
__device__ __half g_tA[8192 * 48];       // [t_hi | t_lo | t_hi]
__device__ __half g_tB[4096 * 48];       // [B''hi | B''hi | B''lo], B''=2B/scale

// ---------------- PTX helpers ----------------
DINLINE uint32_t smem_u32(const void* p) {
    uint32_t a;
    asm("{ .reg .u64 t; cvta.to.shared.u64 t, %1; cvt.u32.u64 %0, t; }"
        : "=r"(a) : "l"(p));
    return a;
}

DINLINE void cpa16(uint32_t s, const void* g) {
    asm volatile("cp.async.cg.shared.global [%0], [%1], 16;" :: "r"(s), "l"(g));
}
#define CP_COMMIT()  asm volatile("cp.async.commit_group;" ::: "memory")
#define CP_WAIT(n)   asm volatile("cp.async.wait_group %0;" :: "n"(n) : "memory")

#define LDSM4(r0, r1, r2, r3, addr)                                              \
    asm volatile("ldmatrix.sync.aligned.m8n8.x4.shared.b16 {%0,%1,%2,%3}, [%4];" \
                 : "=r"(r0), "=r"(r1), "=r"(r2), "=r"(r3) : "r"(addr))

#define MMA16816H(d, a, b)                                                       \
    asm volatile("mma.sync.aligned.m16n8k16.row.col.f32.f16.f16.f32 "            \
                 "{%0,%1,%2,%3}, {%4,%5,%6,%7}, {%8,%9}, {%0,%1,%2,%3};"         \
                 : "+f"((d)[0]), "+f"((d)[1]), "+f"((d)[2]), "+f"((d)[3])        \
                 : "r"((a)[0]), "r"((a)[1]), "r"((a)[2]), "r"((a)[3]),           \
                   "r"((b)[0]), "r"((b)[1]))

// ---------------- kernel 1: signs f32 -> fp16 (exact) ----------------
__global__ __launch_bounds__(256) void s_h_kernel(const float* __restrict__ s) {
    size_t base = ((size_t)blockIdx.x * 256 + threadIdx.x) * 8;
    float4 a = *(const float4*)(s + base);
    float4 b = *(const float4*)(s + base + 4);
    __half2 p0 = __floats2half2_rn(a.x, a.y);
    __half2 p1 = __floats2half2_rn(a.z, a.w);
    __half2 p2 = __floats2half2_rn(b.x, b.y);
    __half2 p3 = __floats2half2_rn(b.z, b.w);
    uint4 o;
    o.x = *(uint32_t*)&p0; o.y = *(uint32_t*)&p1;
    o.z = *(uint32_t*)&p2; o.w = *(uint32_t*)&p3;
    *(uint4*)(g_sh + base) = o;
}

// ---------------- kernel 2: t = x @ lora_A^T (fp32)  +  x -> fp16 ----------
__global__ __launch_bounds__(256) void lora_t_kernel(const float* __restrict__ x,
                                                     const float* __restrict__ A) {
    __shared__ float4 As4[16 * 128];
    __shared__ float ts[64 * 16];
    int tid = threadIdx.x, w = tid >> 5, lane = tid & 31;

    #pragma unroll
    for (int j = 0; j < 4; j++) ts[tid * 4 + j] = 0.f;

    for (int kc = 0; kc < 4096; kc += 512) {
        __syncthreads();
        #pragma unroll
        for (int i = 0; i < 8; i++) {
            int idx = tid + 256 * i;
            int r = idx >> 7, q = idx & 127;
            As4[idx] = *(const float4*)(A + (size_t)r * 4096 + kc + q * 4);
        }
        __syncthreads();
        for (int rr = 0; rr < 8; rr++) {
            int row = blockIdx.x * 64 + w * 8 + rr;
            const float4* xr = (const float4*)(x + (size_t)row * 4096 + kc);
            __half* xo = g_xh + (size_t)row * 4096 + kc;
            float acc[16];
            #pragma unroll
            for (int r = 0; r < 16; r++) acc[r] = 0.f;
            #pragma unroll
            for (int i = 0; i < 4; i++) {
                int kq = lane + i * 32;
                float4 xv = xr[kq];
                __half2 h0 = __floats2half2_rn(xv.x, xv.y);
                __half2 h1 = __floats2half2_rn(xv.z, xv.w);
                uint2 hp;
                hp.x = *(uint32_t*)&h0; hp.y = *(uint32_t*)&h1;
                *(uint2*)(xo + kq * 4) = hp;
                #pragma unroll
                for (int r = 0; r < 16; r++) {
                    float4 av = As4[r * 128 + kq];
                    acc[r] += xv.x * av.x + xv.y * av.y + xv.z * av.z + xv.w * av.w;
                }
            }
            #pragma unroll
            for (int r = 0; r < 16; r++) {
                float v = acc[r];
                v += __shfl_xor_sync(0xFFFFFFFFu, v, 16);
                v += __shfl_xor_sync(0xFFFFFFFFu, v, 8);
                v += __shfl_xor_sync(0xFFFFFFFFu, v, 4);
                v += __shfl_xor_sync(0xFFFFFFFFu, v, 2);
                v += __shfl_xor_sync(0xFFFFFFFFu, v, 1);
                if (lane == 0) ts[(w * 8 + rr) * 16 + r] += v;
            }
        }
    }
    __syncthreads();
    #pragma unroll
    for (int j = 0; j < 4; j++)
        g_t[(size_t)blockIdx.x * 1024 + tid * 4 + j] = ts[tid * 4 + j];
}

// ---------------- kernel 3: pack t -> fp16 [hi | lo | hi] (48/row) ----------
__global__ __launch_bounds__(256) void t_pack_kernel() {
    int row = blockIdx.x * 256 + threadIdx.x;          // < 8192
    const float* t = g_t + (size_t)row * 16;
    __align__(16) __half o[48];
    #pragma unroll
    for (int r = 0; r < 16; r++) {
        float f = t[r];
        __half h = __float2half_rn(f);
        __half l = __float2half_rn(f - __half2float(h));
        o[r] = h; o[16 + r] = l; o[32 + r] = h;
    }
    uint4* dst = (uint4*)(g_tA + (size_t)row * 48);
    const uint4* src = (const uint4*)o;
    #pragma unroll
    for (int j = 0; j < 6; j++) dst[j] = src[j];
}

// ---------------- kernel 4: pack B'' = 2*lora_B/scale -> [hi | hi | lo] -----
__global__ __launch_bounds__(256) void b_pack_kernel(const float* __restrict__ loraB,
                                                     const float* __restrict__ scale) {
    int n = blockIdx.x * 256 + threadIdx.x;            // < 4096
    float inv = 2.0f / scale[n];
    __align__(16) __half o[48];
    #pragma unroll
    for (int r = 0; r < 16; r++) {
        float v = loraB[(size_t)n * 16 + r] * inv;
        __half h = __float2half_rn(v);
        __half l = __float2half_rn(v - __half2float(h));
        o[r] = h; o[16 + r] = h; o[32 + r] = l;
    }
    uint4* dst = (uint4*)(g_tB + (size_t)n * 48);
    const uint4* src = (const uint4*)o;
    #pragma unroll
    for (int j = 0; j < 6; j++) dst[j] = src[j];
}

// ---------------- kernel 5: main fp16 HMMA GEMM ----------------
// CTA 256(M) x 128(N), 512 thr, 16 warps: warp_m = wid>>2 (64 rows),
// warp_n = wid&3 (32 cols). K-chunk 64. Stage: A 256x64 fp16 (32 KB) +
// B 128x64 (16 KB) = 48 KB. 4 stages = 192 KB -> 1 CTA/SM. Single
// __syncthreads per chunk: refill for chunk c+3 targets stage (c-1)&3
// whose readers passed this iteration's barrier.
static constexpr int STAGE = 49152;                    // 32K A + 16K B
static constexpr int NSTAGE = 4;
static constexpr int SMEM_TOTAL = NSTAGE * STAGE;      // 196608

DINLINE void issue_normal(int m0, int n0, int c, uint32_t su, int tid) {
    #pragma unroll
    for (int i = 0; i < 4; i++) {                      // A: 2048 x 16B
        int idx = tid + 512 * i;
        int row = idx >> 3, g = idx & 7;
        uint32_t off = (uint32_t)(row * 128 + g * 16) ^ (uint32_t)((row & 7) << 4);
        cpa16(su + off, g_xh + (size_t)(m0 + row) * 4096 + c * 64 + g * 8);
    }
    #pragma unroll
    for (int i = 0; i < 2; i++) {                      // B: 1024 x 16B
        int idx = tid + 512 * i;
        int row = idx >> 3, g = idx & 7;
        uint32_t off = (uint32_t)(row * 128 + g * 16) ^ (uint32_t)((row & 7) << 4);
        cpa16(su + 32768 + off, g_sh + (size_t)(n0 + row) * 4096 + c * 64 + g * 8);
    }
    CP_COMMIT();
}

DINLINE void issue_lora(int m0, int n0, uint32_t su, int tid) {
    // rows are 48 halves = 96 bytes = SIX 16B groups (the R15 bug was /3,%3).
    // A: 256 rows x 6 = 1536; B: 128 x 6 = 768; total 2304 16B loads.
    #pragma unroll
    for (int i = 0; i < 5; i++) {
        int idx = tid + 512 * i;                       // < 2560
        if (idx < 1536) {
            int row = idx / 6, g = idx % 6;
            uint32_t off = (uint32_t)(row * 128 + g * 16) ^ (uint32_t)((row & 7) << 4);
            cpa16(su + off, g_tA + (size_t)(m0 + row) * 48 + g * 8);
        } else if (idx < 2304) {
            int idx2 = idx - 1536;
            int row = idx2 / 6, g = idx2 % 6;
            uint32_t off = (uint32_t)(row * 128 + g * 16) ^ (uint32_t)((row & 7) << 4);
            cpa16(su + 32768 + off, g_tB + (size_t)(n0 + row) * 48 + g * 8);
        }
    }
    CP_COMMIT();
}

// one k16 step: 2 B-LDSM4 + 4 A-LDSM4 + 16 MMA
#define K16_STEP(k16)                                                            \
    do {                                                                         \
        uint32_t bb[4][2], ah[4][4];                                             \
        _Pragma("unroll")                                                        \
        for (int g = 0; g < 2; g++) {                                            \
            uint32_t addr = Bs +                                                 \
                (((uint32_t)((warp_n * 32 + g * 16 + brow) * 128)                \
                  + (uint32_t)((k16) * 32) + bhalf * 16) ^ sx);                  \
            LDSM4(bb[2 * g][0], bb[2 * g + 1][0],                                \
                  bb[2 * g][1], bb[2 * g + 1][1], addr);                         \
        }                                                                        \
        _Pragma("unroll")                                                        \
        for (int i = 0; i < 4; i++) {                                            \
            uint32_t addr = As +                                                 \
                (((uint32_t)((warp_m * 64 + i * 16 + brow) * 128)                \
                  + (uint32_t)((k16) * 32) + bhalf * 16) ^ sx);                  \
            LDSM4(ah[i][0], ah[i][1], ah[i][2], ah[i][3], addr);                 \
        }                                                                        \
        _Pragma("unroll")                                                        \
        for (int i = 0; i < 4; i++)                                              \
            _Pragma("unroll")                                                    \
            for (int n = 0; n < 4; n++) MMA16816H(acc[i][n], ah[i], bb[n]);      \
    } while (0)

__global__ __launch_bounds__(512, 1) void lora_gemm_kernel(
    const float* __restrict__ scale, float* __restrict__ out) {
    extern __shared__ __align__(1024) char sm[];
    const uint32_t sbase = smem_u32(sm);
    const int tid = threadIdx.x, wid = tid >> 5, l = tid & 31;
    const int warp_m = wid >> 2, warp_n = wid & 3;
    const int n0 = blockIdx.x * 128, m0 = blockIdx.y * 256;

    float acc[4][4][4];
    #pragma unroll
    for (int i = 0; i < 4; i++)
        #pragma unroll
        for (int n = 0; n < 4; n++)
            #pragma unroll
            for (int j = 0; j < 4; j++) acc[i][n][j] = 0.f;

    const uint32_t brow  = (uint32_t)(l & 15);
    const uint32_t bhalf = (uint32_t)(l >> 4);
    const uint32_t sx    = (uint32_t)((l & 7) << 4);

    issue_normal(m0, n0, 0, sbase + 0 * STAGE, tid);
    issue_normal(m0, n0, 1, sbase + 1 * STAGE, tid);
    issue_normal(m0, n0, 2, sbase + 2 * STAGE, tid);

    // chunks 0..63 normal (4x k16) + chunk 64 lora (3x k16); ONE sync per chunk
    for (int c = 0; c <= 64; c++) {
        CP_WAIT(2);                                    // chunk c resident
        __syncthreads();                               // all readers of stage (c-1)&3 done

        // refill stage (c+3)&3 == (c-1)&3 — safe after the barrier above
        if (c + 3 < 64)       issue_normal(m0, n0, c + 3, sbase + (uint32_t)((c + 3) & 3) * STAGE, tid);
        else if (c + 3 == 64) issue_lora(m0, n0, sbase + (uint32_t)((c + 3) & 3) * STAGE, tid);
        else                  CP_COMMIT();             // keep group accounting exact

        const uint32_t As = sbase + (uint32_t)(c & 3) * STAGE;
        const uint32_t Bs = As + 32768;

        if (c < 64) {
            K16_STEP(0);
            K16_STEP(1);
            K16_STEP(2);
            K16_STEP(3);
        } else {
            K16_STEP(0);
            K16_STEP(1);
            K16_STEP(2);
        }
    }

    // ---- epilogue: out = acc * scale[col] ----
    __syncthreads();                                   // lora smem reads done before reuse
    float* sS = (float*)sm;
    if (tid < 128) sS[tid] = scale[n0 + tid];
    __syncthreads();

    #pragma unroll
    for (int i = 0; i < 4; i++) {
        int r0 = m0 + warp_m * 64 + i * 16 + (l >> 2);
        #pragma unroll
        for (int n = 0; n < 4; n++) {
            int cl = warp_n * 32 + n * 8 + (l & 3) * 2;
            float s0 = sS[cl], s1 = sS[cl + 1];
            float2 o0 = make_float2(acc[i][n][0] * s0, acc[i][n][1] * s1);
            float2 o1 = make_float2(acc[i][n][2] * s0, acc[i][n][3] * s1);
            *(float2*)(out + (size_t)r0 * 4096 + n0 + cl) = o0;
            *(float2*)(out + (size_t)(r0 + 8) * 4096 + n0 + cl) = o1;
        }
    }
}

// ---------------- launcher ----------------
extern "C" void kernel_launch(void* const* d_in, const int* in_sizes, int n_in,
                              void* d_out, int out_size) {
    const float* x      = (const float*)d_in[0];
    const float* signs  = (const float*)d_in[1];
    const float* scale  = (const float*)d_in[2];
    const float* lora_A = (const float*)d_in[3];
    const float* lora_B = (const float*)d_in[4];
    float* out = (float*)d_out;

    s_h_kernel<<<8192, 256>>>(signs);
    lora_t_kernel<<<128, 256>>>(x, lora_A);   // also writes g_xh (fused)
    t_pack_kernel<<<32, 256>>>();
    b_pack_kernel<<<16, 256>>>(lora_B, scale);

    cudaFuncSetAttribute(lora_gemm_kernel,
                         cudaFuncAttributeMaxDynamicSharedMemorySize, SMEM_TOTAL);
    lora_gemm_kernel<<<dim3(32, 32), 512, SMEM_TOTAL>>>(scale, out);
}